// round 15
// baseline (speedup 1.0000x reference)
#include <cuda_runtime.h>
#include <cstdint>

// Problem constants
#define BB 32
#define II 2048
#define OO 32
#define CC 16
#define UU 32
#define KTOT (II*CC)        // 32768

// D[1024(m=o*32+u), 32(n=b)] = W^T * X^T
#define MT  8               // m-tiles of 128 rows (4 o x 32 u)
#define KS  64              // k-splits
#define KC  32              // k per chunk (2 i's)
#define NCH (KTOT/(KS*KC))  // 16 chunks per block
#define NBLK (MT*KS)        // 512 CTAs

#define ISTRIDE (OO*CC*UU)  // floats between consecutive i in w

// Accumulator [o][u][b] = 128KB + completion counter. Both zero at module
// load; the last CTA restores both after the squash, so every launch
// (and graph replay) starts from the same state.
__device__ float g_acc[(size_t)OO * UU * BB];
__device__ unsigned g_done;

// ---------------------------------------------------------------------------
__device__ __forceinline__ uint32_t smem_u32(const void* p) {
    uint32_t a;
    asm("{ .reg .u64 t; cvta.to.shared.u64 t, %1; cvt.u32.u64 %0, t; }"
        : "=r"(a) : "l"(p));
    return a;
}
// pack two f32 -> bf16x2, lo in bits[15:0]
__device__ __forceinline__ uint32_t pack_bf16(float lo, float hi) {
    uint32_t r;
    asm("cvt.rn.bf16x2.f32 %0, %1, %2;" : "=r"(r) : "f"(hi), "f"(lo));
    return r;
}
__device__ __forceinline__ void ldsm_x4(uint32_t* r, uint32_t addr) {
    asm volatile("ldmatrix.sync.aligned.m8n8.x4.shared.b16 {%0,%1,%2,%3}, [%4];"
                 : "=r"(r[0]), "=r"(r[1]), "=r"(r[2]), "=r"(r[3]) : "r"(addr));
}
__device__ __forceinline__ void mma_bf16(float* d, const uint32_t* a,
                                         uint32_t b0, uint32_t b1) {
    asm volatile(
        "mma.sync.aligned.m16n8k16.row.col.f32.bf16.bf16.f32 "
        "{%0,%1,%2,%3}, {%4,%5,%6,%7}, {%8,%9}, {%0,%1,%2,%3};"
        : "+f"(d[0]), "+f"(d[1]), "+f"(d[2]), "+f"(d[3])
        : "r"(a[0]), "r"(a[1]), "r"(a[2]), "r"(a[3]), "r"(b0), "r"(b1));
}

// 64B-row swizzle: 16B group j of row r lives at r*64 + ((j ^ ((r>>1)&3))<<4)
__device__ __forceinline__ uint32_t sw64(int row, int grp) {
    return (uint32_t)(row * 64 + ((grp ^ ((row >> 1) & 3)) << 4));
}

// ---------------------------------------------------------------------------
// Fused GEMM + last-CTA squash. grid (MT, KS), 128 threads, 4 CTAs/SM.
// GEMM core = frozen round-7/11 version (validated fastest).
// ---------------------------------------------------------------------------
__global__ void __launch_bounds__(128, 4) gemm_fused(const float* __restrict__ w,
                                                     const float* __restrict__ x,
                                                     float* __restrict__ out) {
    __shared__ __align__(128) uint8_t A_HI[2][128 * 64];
    __shared__ __align__(128) uint8_t A_LO[2][128 * 64];
    __shared__ __align__(128) uint8_t B_HI[2][32 * 64];
    __shared__ __align__(128) uint8_t B_LO[2][32 * 64];
    __shared__ unsigned s_islast;

    const int mt   = blockIdx.x;
    const int ks   = blockIdx.y;
    const int tid  = threadIdx.x;
    const int wid  = tid >> 5;
    const int lane = tid & 31;

    const int o = mt * 4 + wid;
    const int u = lane;
    const int m = tid;

    const int xb = tid >> 2, xq = tid & 3;

    const float* const wbase =
        w + (((size_t)(ks * NCH * 2) * OO + o) * CC) * UU + u;
    const float4* const xbase =
        (const float4*)(x + (size_t)xb * KTOT + ks * (NCH * KC)) + xq * 2;

    float  va[32];
    float4 vb[2];

#pragma unroll
    for (int e = 0; e < 32; e++)
        va[e] = wbase[(size_t)(e >> 4) * ISTRIDE + (e & 15) * UU];
    vb[0] = xbase[0];
    vb[1] = xbase[1];

    float acc[2][4][4];
#pragma unroll
    for (int a = 0; a < 2; a++)
#pragma unroll
        for (int b = 0; b < 4; b++)
#pragma unroll
            for (int c = 0; c < 4; c++) acc[a][b][c] = 0.f;

    for (int t = 0; t < NCH; t++) {
        const int p = t & 1;

#pragma unroll
        for (int j = 0; j < 4; j++) {
            uint32_t h[4], l[4];
#pragma unroll
            for (int q = 0; q < 4; q++) {
                float v0 = va[8 * j + 2 * q], v1 = va[8 * j + 2 * q + 1];
                h[q] = pack_bf16(v0, v1);
                float r0 = v0 - __uint_as_float(h[q] << 16);
                float r1 = v1 - __uint_as_float(h[q] & 0xffff0000u);
                l[q] = pack_bf16(r0, r1);
            }
            const uint32_t off = sw64(m, j);
            *(uint4*)(A_HI[p] + off) = make_uint4(h[0], h[1], h[2], h[3]);
            *(uint4*)(A_LO[p] + off) = make_uint4(l[0], l[1], l[2], l[3]);
        }
        {
            float v[8] = {vb[0].x, vb[0].y, vb[0].z, vb[0].w,
                          vb[1].x, vb[1].y, vb[1].z, vb[1].w};
            uint32_t h[4], l[4];
#pragma unroll
            for (int q = 0; q < 4; q++) {
                h[q] = pack_bf16(v[2 * q], v[2 * q + 1]);
                float r0 = v[2 * q]     - __uint_as_float(h[q] << 16);
                float r1 = v[2 * q + 1] - __uint_as_float(h[q] & 0xffff0000u);
                l[q] = pack_bf16(r0, r1);
            }
            const uint32_t off = sw64(xb, xq);
            *(uint4*)(B_HI[p] + off) = make_uint4(h[0], h[1], h[2], h[3]);
            *(uint4*)(B_LO[p] + off) = make_uint4(l[0], l[1], l[2], l[3]);
        }

        if (t + 1 < NCH) {   // prefetch above barrier (round-11 win)
            const float* wp = wbase + (size_t)((t + 1) * 2) * ISTRIDE;
#pragma unroll
            for (int e = 0; e < 32; e++)
                va[e] = wp[(size_t)(e >> 4) * ISTRIDE + (e & 15) * UU];
            const float4* xp = xbase + (t + 1) * (KC / 4);
            vb[0] = xp[0];
            vb[1] = xp[1];
        }

        __syncthreads();

        const uint32_t aHi = smem_u32(A_HI[p]), aLo = smem_u32(A_LO[p]);
        const uint32_t bHi = smem_u32(B_HI[p]), bLo = smem_u32(B_LO[p]);
#pragma unroll
        for (int kt = 0; kt < 2; kt++) {
            uint32_t ahi[2][4], alo[2][4], bhiR[2][4], bloR[2][4];

            const int ar  = (lane & 7) + ((lane >> 3) & 1) * 8;
            const int akg = 2 * kt + (lane >> 4);
#pragma unroll
            for (int m2 = 0; m2 < 2; m2++) {
                const int row = wid * 32 + m2 * 16 + ar;
                const uint32_t off = sw64(row, akg);
                ldsm_x4(ahi[m2], aHi + off);
                ldsm_x4(alo[m2], aLo + off);
            }
            const int bn  = (lane & 7) + ((lane >> 4) & 1) * 8;
            const int bkg = 2 * kt + ((lane >> 3) & 1);
#pragma unroll
            for (int g2 = 0; g2 < 2; g2++) {
                const int n = g2 * 16 + bn;
                const uint32_t off = sw64(n, bkg);
                ldsm_x4(bhiR[g2], bHi + off);
                ldsm_x4(bloR[g2], bLo + off);
            }
#pragma unroll
            for (int m2 = 0; m2 < 2; m2++)
#pragma unroll
                for (int nt = 0; nt < 4; nt++) {
                    const uint32_t bh0 = bhiR[nt >> 1][(nt & 1) * 2];
                    const uint32_t bh1 = bhiR[nt >> 1][(nt & 1) * 2 + 1];
                    const uint32_t bl0 = bloR[nt >> 1][(nt & 1) * 2];
                    const uint32_t bl1 = bloR[nt >> 1][(nt & 1) * 2 + 1];
                    mma_bf16(acc[m2][nt], ahi[m2], bh0, bh1);
                    mma_bf16(acc[m2][nt], alo[m2], bh0, bh1);
                    mma_bf16(acc[m2][nt], ahi[m2], bl0, bl1);
                }
        }
    }

    // ---- epilogue: accumulate into g_acc[o][u][b] via RED.ADD
    {
        const int gq = lane >> 2, t2 = (lane & 3) * 2;
        float* base = g_acc + (size_t)o * (UU * BB);
#pragma unroll
        for (int m2 = 0; m2 < 2; m2++)
#pragma unroll
            for (int nt = 0; nt < 4; nt++) {
                const int u0 = m2 * 16 + gq;
                const int c  = nt * 8 + t2;
                atomicAdd(base + (size_t)u0 * BB + c,           acc[m2][nt][0]);
                atomicAdd(base + (size_t)u0 * BB + c + 1,       acc[m2][nt][1]);
                atomicAdd(base + (size_t)(u0 + 8) * BB + c,     acc[m2][nt][2]);
                atomicAdd(base + (size_t)(u0 + 8) * BB + c + 1, acc[m2][nt][3]);
            }
    }

    // ---- last-CTA squash (threadFenceReduction pattern)
    __threadfence();
    if (tid == 0) {
        unsigned prev = atomicAdd(&g_done, 1u);
        s_islast = (prev == NBLK - 1) ? 1u : 0u;
    }
    __syncthreads();
    if (s_islast) {
        __threadfence();   // all other CTAs' g_acc atomics are now visible

        // 1024 (o,b) pairs over 128 threads = 8 each; two passes (L2-hot)
        for (int pair = tid; pair < OO * BB; pair += 128) {
            const int oo = pair >> 5, bb = pair & 31;
            const float* ap = g_acc + (size_t)oo * (UU * BB) + bb;

            float nsq = 0.f;
#pragma unroll
            for (int uv = 0; uv < UU; uv++) {
                float sv = ap[uv * BB];
                nsq += sv * sv;
            }
            const float sc = sqrtf(nsq) / (1.0f + nsq);

            float* op = out + (size_t)bb * (OO * UU) + oo * UU;
            float* zp = g_acc + (size_t)oo * (UU * BB) + bb;
#pragma unroll
            for (int uv = 0; uv < UU; uv++) {
                op[uv] = ap[uv * BB] * sc;
                zp[uv * BB] = 0.f;     // restore zero invariant
            }
        }
        __syncthreads();
        if (tid == 0) g_done = 0;      // restore counter for next replay
    }
}

// ---------------------------------------------------------------------------
extern "C" void kernel_launch(void* const* d_in, const int* in_sizes, int n_in,
                              void* d_out, int out_size) {
    const float* x = (const float*)d_in[0];
    const float* w = (const float*)d_in[1];
    if (n_in >= 2 && in_sizes[0] > in_sizes[1]) {   // guard input ordering
        x = (const float*)d_in[1];
        w = (const float*)d_in[0];
    }

    gemm_fused<<<dim3(MT, KS), 128>>>(w, x, (float*)d_out);
}

// round 16
// speedup vs baseline: 1.7321x; 1.7321x over previous
#include <cuda_runtime.h>
#include <cstdint>

// Problem constants
#define BB 32
#define II 2048
#define OO 32
#define CC 16
#define UU 32
#define KTOT (II*CC)        // 32768

// D[1024(m=o*32+u), 32(n=b)] = W^T * X^T
#define MT  8               // m-tiles of 128 rows (4 o x 32 u)
#define KS  64              // k-splits
#define KC  32              // k per chunk (2 i's)
#define NCH (KTOT/(KS*KC))  // 16 chunks per block

#define ISTRIDE (OO*CC*UU)  // floats between consecutive i in w

// Accumulator [o][u][b] = 128KB. Zero at module load; reduce_squash restores
// zeros after reading, so every launch (and graph replay) sees zeros.
__device__ float g_acc[(size_t)OO * UU * BB];

// ---------------------------------------------------------------------------
__device__ __forceinline__ uint32_t smem_u32(const void* p) {
    uint32_t a;
    asm("{ .reg .u64 t; cvta.to.shared.u64 t, %1; cvt.u32.u64 %0, t; }"
        : "=r"(a) : "l"(p));
    return a;
}
// pack two f32 -> bf16x2, lo in bits[15:0]
__device__ __forceinline__ uint32_t pack_bf16(float lo, float hi) {
    uint32_t r;
    asm("cvt.rn.bf16x2.f32 %0, %1, %2;" : "=r"(r) : "f"(hi), "f"(lo));
    return r;
}
__device__ __forceinline__ void ldsm_x4(uint32_t* r, uint32_t addr) {
    asm volatile("ldmatrix.sync.aligned.m8n8.x4.shared.b16 {%0,%1,%2,%3}, [%4];"
                 : "=r"(r[0]), "=r"(r[1]), "=r"(r[2]), "=r"(r[3]) : "r"(addr));
}
__device__ __forceinline__ void mma_bf16(float* d, const uint32_t* a,
                                         uint32_t b0, uint32_t b1) {
    asm volatile(
        "mma.sync.aligned.m16n8k16.row.col.f32.bf16.bf16.f32 "
        "{%0,%1,%2,%3}, {%4,%5,%6,%7}, {%8,%9}, {%0,%1,%2,%3};"
        : "+f"(d[0]), "+f"(d[1]), "+f"(d[2]), "+f"(d[3])
        : "r"(a[0]), "r"(a[1]), "r"(a[2]), "r"(a[3]), "r"(b0), "r"(b1));
}

// 64B-row swizzle: 16B group j of row r lives at r*64 + ((j ^ ((r>>1)&3))<<4)
__device__ __forceinline__ uint32_t sw64(int row, int grp) {
    return (uint32_t)(row * 64 + ((grp ^ ((row >> 1) & 3)) << 4));
}

// ---------------------------------------------------------------------------
// GEMM — FROZEN round-7/11 core + round-14 atomic epilogue. DO NOT MODIFY.
// grid (MT, KS), 128 threads, 4 CTAs/SM, prefetch above barrier.
// ---------------------------------------------------------------------------
__global__ void __launch_bounds__(128, 4) gemm_tc(const float* __restrict__ w,
                                                  const float* __restrict__ x) {
    __shared__ __align__(128) uint8_t A_HI[2][128 * 64];
    __shared__ __align__(128) uint8_t A_LO[2][128 * 64];
    __shared__ __align__(128) uint8_t B_HI[2][32 * 64];
    __shared__ __align__(128) uint8_t B_LO[2][32 * 64];

    const int mt   = blockIdx.x;
    const int ks   = blockIdx.y;
    const int tid  = threadIdx.x;
    const int wid  = tid >> 5;
    const int lane = tid & 31;

    const int o = mt * 4 + wid;
    const int u = lane;
    const int m = tid;

    const int xb = tid >> 2, xq = tid & 3;

    const float* const wbase =
        w + (((size_t)(ks * NCH * 2) * OO + o) * CC) * UU + u;
    const float4* const xbase =
        (const float4*)(x + (size_t)xb * KTOT + ks * (NCH * KC)) + xq * 2;

    float  va[32];
    float4 vb[2];

#pragma unroll
    for (int e = 0; e < 32; e++)
        va[e] = wbase[(size_t)(e >> 4) * ISTRIDE + (e & 15) * UU];
    vb[0] = xbase[0];
    vb[1] = xbase[1];

    float acc[2][4][4];
#pragma unroll
    for (int a = 0; a < 2; a++)
#pragma unroll
        for (int b = 0; b < 4; b++)
#pragma unroll
            for (int c = 0; c < 4; c++) acc[a][b][c] = 0.f;

    for (int t = 0; t < NCH; t++) {
        const int p = t & 1;

#pragma unroll
        for (int j = 0; j < 4; j++) {
            uint32_t h[4], l[4];
#pragma unroll
            for (int q = 0; q < 4; q++) {
                float v0 = va[8 * j + 2 * q], v1 = va[8 * j + 2 * q + 1];
                h[q] = pack_bf16(v0, v1);
                float r0 = v0 - __uint_as_float(h[q] << 16);
                float r1 = v1 - __uint_as_float(h[q] & 0xffff0000u);
                l[q] = pack_bf16(r0, r1);
            }
            const uint32_t off = sw64(m, j);
            *(uint4*)(A_HI[p] + off) = make_uint4(h[0], h[1], h[2], h[3]);
            *(uint4*)(A_LO[p] + off) = make_uint4(l[0], l[1], l[2], l[3]);
        }
        {
            float v[8] = {vb[0].x, vb[0].y, vb[0].z, vb[0].w,
                          vb[1].x, vb[1].y, vb[1].z, vb[1].w};
            uint32_t h[4], l[4];
#pragma unroll
            for (int q = 0; q < 4; q++) {
                h[q] = pack_bf16(v[2 * q], v[2 * q + 1]);
                float r0 = v[2 * q]     - __uint_as_float(h[q] << 16);
                float r1 = v[2 * q + 1] - __uint_as_float(h[q] & 0xffff0000u);
                l[q] = pack_bf16(r0, r1);
            }
            const uint32_t off = sw64(xb, xq);
            *(uint4*)(B_HI[p] + off) = make_uint4(h[0], h[1], h[2], h[3]);
            *(uint4*)(B_LO[p] + off) = make_uint4(l[0], l[1], l[2], l[3]);
        }

        if (t + 1 < NCH) {   // prefetch above barrier (round-11 win)
            const float* wp = wbase + (size_t)((t + 1) * 2) * ISTRIDE;
#pragma unroll
            for (int e = 0; e < 32; e++)
                va[e] = wp[(size_t)(e >> 4) * ISTRIDE + (e & 15) * UU];
            const float4* xp = xbase + (t + 1) * (KC / 4);
            vb[0] = xp[0];
            vb[1] = xp[1];
        }

        __syncthreads();

        const uint32_t aHi = smem_u32(A_HI[p]), aLo = smem_u32(A_LO[p]);
        const uint32_t bHi = smem_u32(B_HI[p]), bLo = smem_u32(B_LO[p]);
#pragma unroll
        for (int kt = 0; kt < 2; kt++) {
            uint32_t ahi[2][4], alo[2][4], bhiR[2][4], bloR[2][4];

            const int ar  = (lane & 7) + ((lane >> 3) & 1) * 8;
            const int akg = 2 * kt + (lane >> 4);
#pragma unroll
            for (int m2 = 0; m2 < 2; m2++) {
                const int row = wid * 32 + m2 * 16 + ar;
                const uint32_t off = sw64(row, akg);
                ldsm_x4(ahi[m2], aHi + off);
                ldsm_x4(alo[m2], aLo + off);
            }
            const int bn  = (lane & 7) + ((lane >> 4) & 1) * 8;
            const int bkg = 2 * kt + ((lane >> 3) & 1);
#pragma unroll
            for (int g2 = 0; g2 < 2; g2++) {
                const int n = g2 * 16 + bn;
                const uint32_t off = sw64(n, bkg);
                ldsm_x4(bhiR[g2], bHi + off);
                ldsm_x4(bloR[g2], bLo + off);
            }
#pragma unroll
            for (int m2 = 0; m2 < 2; m2++)
#pragma unroll
                for (int nt = 0; nt < 4; nt++) {
                    const uint32_t bh0 = bhiR[nt >> 1][(nt & 1) * 2];
                    const uint32_t bh1 = bhiR[nt >> 1][(nt & 1) * 2 + 1];
                    const uint32_t bl0 = bloR[nt >> 1][(nt & 1) * 2];
                    const uint32_t bl1 = bloR[nt >> 1][(nt & 1) * 2 + 1];
                    mma_bf16(acc[m2][nt], ahi[m2], bh0, bh1);
                    mma_bf16(acc[m2][nt], alo[m2], bh0, bh1);
                    mma_bf16(acc[m2][nt], ahi[m2], bl0, bl1);
                }
        }
    }

    // ---- epilogue: accumulate into g_acc[o][u][b] via RED.ADD
    {
        const int gq = lane >> 2, t2 = (lane & 3) * 2;
        float* base = g_acc + (size_t)o * (UU * BB);
#pragma unroll
        for (int m2 = 0; m2 < 2; m2++)
#pragma unroll
            for (int nt = 0; nt < 4; nt++) {
                const int u0 = m2 * 16 + gq;
                const int c  = nt * 8 + t2;
                atomicAdd(base + (size_t)u0 * BB + c,           acc[m2][nt][0]);
                atomicAdd(base + (size_t)u0 * BB + c + 1,       acc[m2][nt][1]);
                atomicAdd(base + (size_t)(u0 + 8) * BB + c,     acc[m2][nt][2]);
                atomicAdd(base + (size_t)(u0 + 8) * BB + c + 1, acc[m2][nt][3]);
            }
    }
}

// ---------------------------------------------------------------------------
// Squash (PDL secondary): launch overlaps gemm; the grid-dependency sync
// releases when gemm completes (all g_acc atomics visible). Restores zeros.
// ---------------------------------------------------------------------------
__global__ void __launch_bounds__(1024) reduce_squash(float* __restrict__ out) {
    cudaGridDependencySynchronize();   // wait for gemm_tc completion

    const int o = blockIdx.x;
    const int t = threadIdx.x;
    const int uu = t >> 5, b = t & 31;

    __shared__ float sblk[UU * 33];    // [u][b] padded
    __shared__ float scale_s[BB];

    float* ap = g_acc + ((size_t)o * UU + uu) * BB + b;
    sblk[uu * 33 + b] = *ap;   // coalesced 128B rows (L2-hot)
    *ap = 0.f;                 // restore invariant for next launch/replay
    __syncthreads();

    if (t < BB) {
        float nsq = 0.f;
#pragma unroll
        for (int uv = 0; uv < UU; uv++) {
            float sv = sblk[uv * 33 + t];
            nsq += sv * sv;
        }
        scale_s[t] = sqrtf(nsq) / (1.0f + nsq);
    }
    __syncthreads();

    {   // coalesced output: b2 = t>>5, u2 = t&31
        const int b2 = t >> 5, u2 = t & 31;
        out[(size_t)b2 * (OO * UU) + o * UU + u2] =
            sblk[u2 * 33 + b2] * scale_s[b2];
    }
}

// ---------------------------------------------------------------------------
extern "C" void kernel_launch(void* const* d_in, const int* in_sizes, int n_in,
                              void* d_out, int out_size) {
    const float* x = (const float*)d_in[0];
    const float* w = (const float*)d_in[1];
    if (n_in >= 2 && in_sizes[0] > in_sizes[1]) {   // guard input ordering
        x = (const float*)d_in[1];
        w = (const float*)d_in[0];
    }

    gemm_tc<<<dim3(MT, KS), 128>>>(w, x);

    // PDL launch: reduce's ramp overlaps gemm execution.
    cudaLaunchConfig_t cfg = {};
    cfg.gridDim  = dim3(OO, 1, 1);
    cfg.blockDim = dim3(1024, 1, 1);
    cudaLaunchAttribute attrs[1];
    attrs[0].id = cudaLaunchAttributeProgrammaticStreamSerialization;
    attrs[0].val.programmaticStreamSerializationAllowed = 1;
    cfg.attrs = attrs;
    cfg.numAttrs = 1;
    float* outp = (float*)d_out;
    if (cudaLaunchKernelEx(&cfg, reduce_squash, outp) != cudaSuccess) {
        reduce_squash<<<OO, 1024>>>(outp);   // fallback: plain ordering
    }
}